// round 13
// baseline (speedup 1.0000x reference)
#include <cuda_runtime.h>
#include <math_constants.h>

// Problem constants (fixed instance: B=4, L=4096, H=8, D=64, sample_k=n_top=45)
#define Bq  4
#define Lq  4096
#define Hq  8
#define Dq  64
#define Sq  45
#define Uq  45
#define BHq 32
#define NKC 16      // key chunks for flash attn (256 keys each)
#define KCS 256
#define NB  8       // stage-1 key buckets (512 keys each)
#define MAXP 32768
#define PCAP 4096   // smem pair-slab capacity per 512-l block (mean 2880, sd ~54)

// ---------------- scratch (device globals: alloc-free) ----------------
__device__ int   g_top[BHq * Uq];
__device__ int   g_umap[BHq * Lq];              // l -> u (or -1)
__device__ float g_part[BHq * NKC * Uq * Dq];
__device__ float g_cm[BHq * NKC * Uq];
__device__ float g_cs[BHq * NKC * Uq];
__device__ float g_meanp[BHq * 16 * Dq];
__device__ float g_meanv[BHq * Dq];
// stage-1 bucketed structures (idx shared across all (b,h): build once)
__device__ int   g_cnt[Lq * NB];
__device__ int   g_off[NB * Lq];
__device__ int   g_btot[NB];
__device__ int   g_pairs[NB * MAXP];
__device__ int   g_perm[NB * Lq];               // per (bucket, 512-l block): rank -> l-offset
__device__ float g_pm2[(size_t)BHq * Lq * NB];
__device__ float g_ps2[(size_t)BHq * Lq * NB];

// ---- cp.async helpers ----
__device__ __forceinline__ void cp_async16(void* smem_dst, const void* gsrc) {
    unsigned s = (unsigned)__cvta_generic_to_shared(smem_dst);
    asm volatile("cp.async.ca.shared.global [%0], [%1], 16;\n" :: "r"(s), "l"(gsrc));
}
__device__ __forceinline__ void cp_async_wait_all() {
    asm volatile("cp.async.commit_group;\n");
    asm volatile("cp.async.wait_group 0;\n");
}

// ---------------- Stage 0a: per-(l,bucket) counts ----------------
__global__ void __launch_bounds__(256) kernel_cnt(const int* __restrict__ idx) {
    int l = blockIdx.x * 256 + threadIdx.x;
    if (l >= Lq) return;
    int c[NB];
#pragma unroll
    for (int b = 0; b < NB; b++) c[b] = 0;
    for (int s = 0; s < Sq; s++) c[idx[l * Sq + s] >> 9]++;
#pragma unroll
    for (int b = 0; b < NB; b++) g_cnt[l * NB + b] = c[b];
}

// ---------------- Stage 0b: per-bucket exclusive scan over l ----------------
__global__ void __launch_bounds__(256) kernel_scan() {
    int bucket = blockIdx.x;
    int t = threadIdx.x;
    __shared__ int ps[256];
    int loc[16];
    int s = 0;
#pragma unroll
    for (int i = 0; i < 16; i++) { loc[i] = s; s += g_cnt[(t * 16 + i) * NB + bucket]; }
    ps[t] = s;
    __syncthreads();
    for (int o = 1; o < 256; o <<= 1) {
        int v = (t >= o) ? ps[t - o] : 0;
        __syncthreads();
        ps[t] += v;
        __syncthreads();
    }
    int excl = (t == 0) ? 0 : ps[t - 1];
#pragma unroll
    for (int i = 0; i < 16; i++) g_off[bucket * Lq + t * 16 + i] = excl + loc[i];
    if (t == 255) g_btot[bucket] = ps[255];
}

// ---------------- Stage 0c: deterministic scatter ----------------
__global__ void __launch_bounds__(256) kernel_scatter(const int* __restrict__ idx) {
    int l = blockIdx.x * 256 + threadIdx.x;
    if (l >= Lq) return;
    int c[NB];
#pragma unroll
    for (int b = 0; b < NB; b++) c[b] = 0;
    for (int s = 0; s < Sq; s++) {
        int j = idx[l * Sq + s];
        int b = j >> 9;
        int pos = g_off[b * Lq + l] + c[b];
        if (pos < MAXP) g_pairs[b * MAXP + pos] = j & 511;
        c[b]++;
    }
}

// ---------------- Stage 0d: count-sorted rank per (bucket, 512-l block) ----------------
// Stable sort by (cnt desc, l asc) via brute-force rank: 512 broadcast smem
// reads per thread. perm[rank] = l-offset; warp lanes then carry near-equal
// trip counts in stage 1 (divergence waste 1.5 -> ~1.05).
__global__ void __launch_bounds__(512) kernel_perm() {
    int bucket = blockIdx.x, blk = blockIdx.y;
    int t = threadIdx.x;
    __shared__ int scnt[512];
    int cnt = g_cnt[(blk * 512 + t) * NB + bucket];
    scnt[t] = cnt;
    __syncthreads();
    int rank = 0;
    for (int i = 0; i < 512; i++) {
        int c = scnt[i];
        rank += (c > cnt) || (c == cnt && i < t);
    }
    g_perm[bucket * Lq + blk * 512 + rank] = t;
}

// ---------------- Stage 1: bucketed sampled QK^T, count-balanced threads ----------------
__global__ void __launch_bounds__(512, 1) kernel_m5(const float* __restrict__ Q,
                                                    const float* __restrict__ K) {
    extern __shared__ float smem[];
    float* ks = smem;                          // 512*64 floats swizzled (131072 B)
    float* qb = smem + 512 * 64;               // 256*64 floats swizzled (65536 B)
    int*   sp = (int*)(smem + 512 * 64 + 256 * 64);   // PCAP ints

    int bucket = blockIdx.x, bh = blockIdx.y, z = blockIdx.z;
    int b = bh >> 3, h = bh & 7;
    int tid = threadIdx.x;

    const float* Kbase = K + (((size_t)b * Lq + bucket * 512) * Hq + h) * Dq;
    for (int e = tid; e < 512 * 16; e += 512) {
        int r = e >> 4, i = e & 15;
        cp_async16(ks + (r * 16 + (i ^ (r & 15))) * 4, Kbase + (size_t)r * 512 + i * 4);
    }
    asm volatile("cp.async.commit_group;\n");

    for (int it = 0; it < 4; it++) {
        int l0 = z * 2048 + it * 512;
        int blk = z * 4 + it;
        if (it) __syncthreads();

        int myrow = g_perm[bucket * Lq + blk * 512 + tid];   // count-balanced l
        int l = l0 + myrow;
        int cnt = g_cnt[l * NB + bucket];

        int pairlo = g_off[bucket * Lq + l0];
        int pairhi = (l0 + 512 < Lq) ? g_off[bucket * Lq + l0 + 512] : g_btot[bucket];
        int nl = pairhi - pairlo; if (nl > PCAP) nl = PCAP;
        for (int e = tid; e < nl; e += 512) sp[e] = g_pairs[bucket * MAXP + pairlo + e];

        const float* Qbase = Q + (((size_t)b * Lq + l0) * Hq + h) * Dq;
        float4 q[16];

        // phase A: stage block rows 0..255; threads with myrow<256 grab
        for (int e = tid; e < 256 * 16; e += 512) {
            int r = e >> 4, i = e & 15;
            cp_async16(qb + (r * 16 + (i ^ (r & 15))) * 4, Qbase + (size_t)r * 512 + i * 4);
        }
        cp_async_wait_all();
        __syncthreads();
        if (myrow < 256) {
            int r = myrow;
#pragma unroll
            for (int i = 0; i < 16; i++) q[i] = ((const float4*)qb)[r * 16 + (i ^ (r & 15))];
        }
        __syncthreads();
        // phase B: stage rows 256..511; rest grab
        for (int e = tid; e < 256 * 16; e += 512) {
            int r = e >> 4, i = e & 15;
            cp_async16(qb + (r * 16 + (i ^ (r & 15))) * 4, Qbase + (size_t)(256 + r) * 512 + i * 4);
        }
        cp_async_wait_all();
        __syncthreads();
        if (myrow >= 256) {
            int r = myrow - 256;
#pragma unroll
            for (int i = 0; i < 16; i++) q[i] = ((const float4*)qb)[r * 16 + (i ^ (r & 15))];
        }
        __syncthreads();

        int lst = g_off[bucket * Lq + l] - pairlo;

        float lm = -CUDART_INF_F, lsum = 0.f;
        for (int p = 0; p < cnt; p++) {
            int pi = lst + p;
            int jloc = (pi < PCAP) ? sp[pi] : g_pairs[bucket * MAXP + pairlo + pi];
            const float4* kr = (const float4*)ks + jloc * 16;
            int sw = jloc & 15;
            float a0 = 0.f, a1 = 0.f, a2 = 0.f, a3 = 0.f;
#pragma unroll
            for (int i = 0; i < 4; i++) {
                float4 k0 = kr[(4 * i + 0) ^ sw];
                float4 k1 = kr[(4 * i + 1) ^ sw];
                float4 k2 = kr[(4 * i + 2) ^ sw];
                float4 k3 = kr[(4 * i + 3) ^ sw];
                float4 q0 = q[4 * i + 0], q1 = q[4 * i + 1];
                float4 q2 = q[4 * i + 2], q3 = q[4 * i + 3];
                a0 = fmaf(q0.x, k0.x, a0); a0 = fmaf(q0.y, k0.y, a0);
                a0 = fmaf(q0.z, k0.z, a0); a0 = fmaf(q0.w, k0.w, a0);
                a1 = fmaf(q1.x, k1.x, a1); a1 = fmaf(q1.y, k1.y, a1);
                a1 = fmaf(q1.z, k1.z, a1); a1 = fmaf(q1.w, k1.w, a1);
                a2 = fmaf(q2.x, k2.x, a2); a2 = fmaf(q2.y, k2.y, a2);
                a2 = fmaf(q2.z, k2.z, a2); a2 = fmaf(q2.w, k2.w, a2);
                a3 = fmaf(q3.x, k3.x, a3); a3 = fmaf(q3.y, k3.y, a3);
                a3 = fmaf(q3.z, k3.z, a3); a3 = fmaf(q3.w, k3.w, a3);
            }
            float dot = (a0 + a1) + (a2 + a3);
            lm = fmaxf(lm, dot);
            lsum += dot;
        }
        size_t o = ((size_t)bh * Lq + l) * NB + bucket;
        g_pm2[o] = lm;
        g_ps2[o] = lsum;
    }
}

// ---------------- Stage 2: fused M-combine + top-45 + umap ----------------
__global__ void __launch_bounds__(256) kernel_topk() {
    int bh = blockIdx.x;
    __shared__ float v[Lq];
    __shared__ float bv[256];
    __shared__ int   bi[256];
    int t = threadIdx.x;
    for (int i = t; i < Lq; i += 256) {
        size_t base = ((size_t)bh * Lq + i) * NB;
        float m = -CUDART_INF_F, s = 0.f;
#pragma unroll
        for (int b = 0; b < NB; b++) {
            m = fmaxf(m, g_pm2[base + b]);
            s += g_ps2[base + b];
        }
        v[i] = m - s * (1.f / Lq);
        g_umap[bh * Lq + i] = -1;
    }
    __syncthreads();
    for (int u = 0; u < Uq; u++) {
        float best = -CUDART_INF_F;
        int   besti = Lq;
        for (int i = t; i < Lq; i += 256) {
            float x = v[i];
            if (x > best) { best = x; besti = i; }
        }
        bv[t] = best; bi[t] = besti;
        __syncthreads();
        for (int st = 128; st > 0; st >>= 1) {
            if (t < st) {
                if (bv[t + st] > bv[t] || (bv[t + st] == bv[t] && bi[t + st] < bi[t])) {
                    bv[t] = bv[t + st]; bi[t] = bi[t + st];
                }
            }
            __syncthreads();
        }
        if (t == 0) {
            g_top[bh * Uq + u] = bi[0];
            g_umap[bh * Lq + bi[0]] = u;
            v[bi[0]] = -CUDART_INF_F;
        }
        __syncthreads();
    }
}

// ---------------- Stage 3: flash-style scores+softmax+attnV per (bh, 256-key chunk) ----
__global__ void __launch_bounds__(256) kernel_attn(const float* __restrict__ Q,
                                                   const float* __restrict__ K,
                                                   const float* __restrict__ V) {
    __shared__ float Qs[Uq * 65];
    __shared__ float Ks[64 * 65];
    __shared__ float Vs[64 * 65];
    __shared__ float Ws[Uq * 65];
    int bh = blockIdx.y, kc = blockIdx.x;
    int b = bh >> 3, h = bh & 7;
    int tid = threadIdx.x;

    for (int e = tid; e < Uq * Dq; e += 256) {
        int u = e >> 6, d = e & 63;
        int row = g_top[bh * Uq + u];
        Qs[u * 65 + d] = Q[(((size_t)b * Lq + row) * Hq + h) * Dq + d];
    }
    int tu = tid >> 4, tk = tid & 15;
    float m_run[3], s_run[3], acc[3][4];
#pragma unroll
    for (int r = 0; r < 3; r++) {
        m_run[r] = -CUDART_INF_F; s_run[r] = 0.f;
#pragma unroll
        for (int j = 0; j < 4; j++) acc[r][j] = 0.f;
    }

    for (int sub = 0; sub < KCS / 64; sub++) {
        int k0 = kc * KCS + sub * 64;
        __syncthreads();
        for (int e = tid; e < 64 * Dq; e += 256) {
            int k = e >> 6, d = e & 63;
            size_t go = (((size_t)b * Lq + k0 + k) * Hq + h) * Dq + d;
            Ks[k * 65 + d] = K[go];
            Vs[k * 65 + d] = V[go];
        }
        __syncthreads();

        float sc[3][4];
#pragma unroll
        for (int r = 0; r < 3; r++)
#pragma unroll
            for (int j = 0; j < 4; j++) sc[r][j] = 0.f;
#pragma unroll 4
        for (int d = 0; d < 64; d++) {
            float qv[3];
#pragma unroll
            for (int r = 0; r < 3; r++) {
                int u = tu + 16 * r;
                qv[r] = (u < Uq) ? Qs[u * 65 + d] : 0.f;
            }
            float kv[4];
#pragma unroll
            for (int j = 0; j < 4; j++) kv[j] = Ks[(tk + 16 * j) * 65 + d];
#pragma unroll
            for (int r = 0; r < 3; r++)
#pragma unroll
                for (int j = 0; j < 4; j++) sc[r][j] = fmaf(qv[r], kv[j], sc[r][j]);
        }

#pragma unroll
        for (int r = 0; r < 3; r++) {
            int u = tu + 16 * r;
#pragma unroll
            for (int j = 0; j < 4; j++) sc[r][j] *= 0.125f;
            float bm = fmaxf(fmaxf(sc[r][0], sc[r][1]), fmaxf(sc[r][2], sc[r][3]));
#pragma unroll
            for (int o = 8; o > 0; o >>= 1)
                bm = fmaxf(bm, __shfl_xor_sync(0xffffffffu, bm, o));
            float mnew = fmaxf(m_run[r], bm);
            float f = expf(m_run[r] - mnew);
#pragma unroll
            for (int j = 0; j < 4; j++) acc[r][j] *= f;
            s_run[r] *= f;
            float w[4], ws = 0.f;
#pragma unroll
            for (int j = 0; j < 4; j++) { w[j] = expf(sc[r][j] - mnew); ws += w[j]; }
#pragma unroll
            for (int o = 8; o > 0; o >>= 1)
                ws += __shfl_xor_sync(0xffffffffu, ws, o);
            s_run[r] += ws;
            m_run[r] = mnew;
            if (u < Uq) {
#pragma unroll
                for (int j = 0; j < 4; j++) Ws[u * 65 + tk + 16 * j] = w[j];
            }
        }
        __syncthreads();

#pragma unroll 4
        for (int k = 0; k < 64; k++) {
            float wv[3];
#pragma unroll
            for (int r = 0; r < 3; r++) {
                int u = tu + 16 * r;
                wv[r] = (u < Uq) ? Ws[u * 65 + k] : 0.f;
            }
            float vv[4];
#pragma unroll
            for (int j = 0; j < 4; j++) vv[j] = Vs[k * 65 + tk + 16 * j];
#pragma unroll
            for (int r = 0; r < 3; r++)
#pragma unroll
                for (int j = 0; j < 4; j++) acc[r][j] = fmaf(wv[r], vv[j], acc[r][j]);
        }
    }

#pragma unroll
    for (int r = 0; r < 3; r++) {
        int u = tu + 16 * r;
        if (u < Uq) {
#pragma unroll
            for (int j = 0; j < 4; j++)
                g_part[((bh * NKC + kc) * Uq + u) * Dq + tk + 16 * j] = acc[r][j];
            if (tk == 0) {
                g_cm[(bh * NKC + kc) * Uq + u] = m_run[r];
                g_cs[(bh * NKC + kc) * Uq + u] = s_run[r];
            }
        }
    }
}

// ---------------- Stage 4: V mean ----------------
__global__ void __launch_bounds__(256) kernel_meanpart(const float* __restrict__ V) {
    int lc = blockIdx.x;
    int bh = blockIdx.y;
    int b = bh >> 3, h = bh & 7;
    int tid = threadIdx.x;
    int d = tid & 63, c = tid >> 6;
    __shared__ float red[256];
    float s = 0.f;
    int lb = lc * 256 + c * 64;
    for (int i = 0; i < 64; i++)
        s += V[(((size_t)b * Lq + lb + i) * Hq + h) * Dq + d];
    red[tid] = s;
    __syncthreads();
    if (c == 0)
        g_meanp[(bh * 16 + lc) * Dq + d] = red[d] + red[64 + d] + red[128 + d] + red[192 + d];
}

__global__ void __launch_bounds__(256) kernel_meancomb() {
    int e = blockIdx.x * 256 + threadIdx.x;
    if (e >= BHq * Dq) return;
    int bh = e >> 6, d = e & 63;
    float s = 0.f;
#pragma unroll
    for (int lc = 0; lc < 16; lc++) s += g_meanp[(bh * 16 + lc) * Dq + d];
    g_meanv[bh * Dq + d] = s * (1.f / Lq);
}

// ---------------- Stage 5: single output kernel (mean fill OR top-row result) ----------
__global__ void __launch_bounds__(256) kernel_out(float4* __restrict__ out) {
    int i = blockIdx.x * 256 + threadIdx.x;      // float4 index, 2,097,152
    int row = i >> 4;                            // (bh,l) flat
    int d4 = i & 15;
    int bh = row >> 12;
    int u = g_umap[row];
    if (u < 0) {
        out[i] = ((const float4*)g_meanv)[bh * 16 + d4];
    } else {
        float M = -CUDART_INF_F;
#pragma unroll
        for (int c = 0; c < NKC; c++) M = fmaxf(M, g_cm[(bh * NKC + c) * Uq + u]);
        float S = 0.f;
        float4 A = make_float4(0.f, 0.f, 0.f, 0.f);
#pragma unroll
        for (int c = 0; c < NKC; c++) {
            float f = expf(g_cm[(bh * NKC + c) * Uq + u] - M);
            S += g_cs[(bh * NKC + c) * Uq + u] * f;
            float4 p = ((const float4*)g_part)[((bh * NKC + c) * Uq + u) * 16 + d4];
            A.x += p.x * f; A.y += p.y * f; A.z += p.z * f; A.w += p.w * f;
        }
        float inv = 1.f / S;
        out[i] = make_float4(A.x * inv, A.y * inv, A.z * inv, A.w * inv);
    }
}

// ---------------- launch ----------------
extern "C" void kernel_launch(void* const* d_in, const int* in_sizes, int n_in,
                              void* d_out, int out_size) {
    const float* Q   = (const float*)d_in[0];
    const float* K   = (const float*)d_in[1];
    const float* V   = (const float*)d_in[2];
    const int*   idx = (const int*)d_in[3];
    float* out = (float*)d_out;

    const int M5_SMEM = (512 * 64 + 256 * 64) * 4 + PCAP * 4;   // 212,992 B
    static bool attr_set = false;
    if (!attr_set) {
        cudaFuncSetAttribute(kernel_m5, cudaFuncAttributeMaxDynamicSharedMemorySize, M5_SMEM);
        attr_set = true;
    }

    kernel_cnt     <<<Lq / 256, 256>>>(idx);
    kernel_scan    <<<NB, 256>>>();
    kernel_scatter <<<Lq / 256, 256>>>(idx);
    kernel_perm    <<<dim3(NB, Lq / 512), 512>>>();
    kernel_m5      <<<dim3(NB, BHq, 2), 512, M5_SMEM>>>(Q, K);
    kernel_topk    <<<BHq, 256>>>();
    kernel_attn    <<<dim3(NKC, BHq), 256>>>(Q, K, V);
    kernel_meanpart<<<dim3(16, BHq), 256>>>(V);
    kernel_meancomb<<<(BHq * Dq + 255) / 256, 256>>>();
    kernel_out     <<<(BHq * Lq * Dq / 4) / 256, 256>>>((float4*)out);
}

// round 14
// speedup vs baseline: 1.1142x; 1.1142x over previous
#include <cuda_runtime.h>
#include <math_constants.h>

// Problem constants (fixed instance: B=4, L=4096, H=8, D=64, sample_k=n_top=45)
#define Bq  4
#define Lq  4096
#define Hq  8
#define Dq  64
#define Sq  45
#define Uq  45
#define BHq 32
#define NKC 16      // key chunks for flash attn (256 keys each)
#define KCS 256
#define NB  8       // stage-1 key buckets (512 keys each)
#define MAXP 32768
#define PCAP 4096   // smem pair-slab capacity per 512-l block (mean 2880, sd ~54)

// ---------------- scratch (device globals: alloc-free) ----------------
__device__ int   g_top[BHq * Uq];
__device__ int   g_umap[BHq * Lq];              // l -> u (or -1)
__device__ float g_part[BHq * NKC * Uq * Dq];
__device__ float g_cm[BHq * NKC * Uq];
__device__ float g_cs[BHq * NKC * Uq];
__device__ float g_meanp[BHq * 16 * Dq];
__device__ float g_meanv[BHq * Dq];
// stage-1 bucketed structures (idx shared across all (b,h): build once)
__device__ int   g_cnt[Lq * NB];
__device__ int   g_off[NB * Lq];
__device__ int   g_btot[NB];
__device__ int   g_pairs[NB * MAXP];
__device__ float g_pm2[(size_t)BHq * Lq * NB];
__device__ float g_ps2[(size_t)BHq * Lq * NB];

// ---- cp.async helpers ----
__device__ __forceinline__ void cp_async16(void* smem_dst, const void* gsrc) {
    unsigned s = (unsigned)__cvta_generic_to_shared(smem_dst);
    asm volatile("cp.async.ca.shared.global [%0], [%1], 16;\n" :: "r"(s), "l"(gsrc));
}
__device__ __forceinline__ void cp_async_wait_all() {
    asm volatile("cp.async.commit_group;\n");
    asm volatile("cp.async.wait_group 0;\n");
}

// ---------------- Stage 0a: per-(l,bucket) counts ----------------
__global__ void __launch_bounds__(256) kernel_cnt(const int* __restrict__ idx) {
    int l = blockIdx.x * 256 + threadIdx.x;
    if (l >= Lq) return;
    int c[NB];
#pragma unroll
    for (int b = 0; b < NB; b++) c[b] = 0;
    for (int s = 0; s < Sq; s++) c[idx[l * Sq + s] >> 9]++;
#pragma unroll
    for (int b = 0; b < NB; b++) g_cnt[l * NB + b] = c[b];
}

// ---------------- Stage 0b: per-bucket exclusive scan over l ----------------
__global__ void __launch_bounds__(256) kernel_scan() {
    int bucket = blockIdx.x;
    int t = threadIdx.x;
    __shared__ int ps[256];
    int loc[16];
    int s = 0;
#pragma unroll
    for (int i = 0; i < 16; i++) { loc[i] = s; s += g_cnt[(t * 16 + i) * NB + bucket]; }
    ps[t] = s;
    __syncthreads();
    for (int o = 1; o < 256; o <<= 1) {
        int v = (t >= o) ? ps[t - o] : 0;
        __syncthreads();
        ps[t] += v;
        __syncthreads();
    }
    int excl = (t == 0) ? 0 : ps[t - 1];
#pragma unroll
    for (int i = 0; i < 16; i++) g_off[bucket * Lq + t * 16 + i] = excl + loc[i];
    if (t == 255) g_btot[bucket] = ps[255];
}

// ---------------- Stage 0c: deterministic scatter ----------------
__global__ void __launch_bounds__(256) kernel_scatter(const int* __restrict__ idx) {
    int l = blockIdx.x * 256 + threadIdx.x;
    if (l >= Lq) return;
    int c[NB];
#pragma unroll
    for (int b = 0; b < NB; b++) c[b] = 0;
    for (int s = 0; s < Sq; s++) {
        int j = idx[l * Sq + s];
        int b = j >> 9;
        int pos = g_off[b * Lq + l] + c[b];
        if (pos < MAXP) g_pairs[b * MAXP + pos] = j & 511;
        c[b]++;
    }
}

// ---------------- Stage 1: bucketed sampled QK^T, 512 threads / 16 warps ----------------
__global__ void __launch_bounds__(512, 1) kernel_m5(const float* __restrict__ Q,
                                                    const float* __restrict__ K) {
    extern __shared__ float smem[];
    float* ks = smem;                          // 512*64 floats swizzled (131072 B)
    float* qb = smem + 512 * 64;               // 256*64 floats swizzled (65536 B)
    int*   sp = (int*)(smem + 512 * 64 + 256 * 64);   // PCAP ints

    int bucket = blockIdx.x, bh = blockIdx.y, z = blockIdx.z;
    int b = bh >> 3, h = bh & 7;
    int tid = threadIdx.x;

    const float* Kbase = K + (((size_t)b * Lq + bucket * 512) * Hq + h) * Dq;
    for (int e = tid; e < 512 * 16; e += 512) {
        int r = e >> 4, i = e & 15;
        cp_async16(ks + (r * 16 + (i ^ (r & 15))) * 4, Kbase + (size_t)r * 512 + i * 4);
    }
    asm volatile("cp.async.commit_group;\n");

    for (int it = 0; it < 4; it++) {
        int l0 = z * 2048 + it * 512;
        if (it) __syncthreads();

        int pairlo = g_off[bucket * Lq + l0];
        int pairhi = (l0 + 512 < Lq) ? g_off[bucket * Lq + l0 + 512] : g_btot[bucket];
        int nl = pairhi - pairlo; if (nl > PCAP) nl = PCAP;
        for (int e = tid; e < nl; e += 512) sp[e] = g_pairs[bucket * MAXP + pairlo + e];

        const float* Qbase = Q + (((size_t)b * Lq + l0) * Hq + h) * Dq;
        float4 q[16];

        for (int e = tid; e < 256 * 16; e += 512) {
            int r = e >> 4, i = e & 15;
            cp_async16(qb + (r * 16 + (i ^ (r & 15))) * 4, Qbase + (size_t)r * 512 + i * 4);
        }
        cp_async_wait_all();
        __syncthreads();
        if (tid < 256) {
            int r = tid;
#pragma unroll
            for (int i = 0; i < 16; i++) q[i] = ((const float4*)qb)[r * 16 + (i ^ (r & 15))];
        }
        __syncthreads();
        for (int e = tid; e < 256 * 16; e += 512) {
            int r = e >> 4, i = e & 15;
            cp_async16(qb + (r * 16 + (i ^ (r & 15))) * 4, Qbase + (size_t)(256 + r) * 512 + i * 4);
        }
        cp_async_wait_all();
        __syncthreads();
        if (tid >= 256) {
            int r = tid - 256;
#pragma unroll
            for (int i = 0; i < 16; i++) q[i] = ((const float4*)qb)[r * 16 + (i ^ (r & 15))];
        }
        __syncthreads();

        int l = l0 + tid;
        int cnt = g_cnt[l * NB + bucket];
        int lst = g_off[bucket * Lq + l] - pairlo;

        float lm = -CUDART_INF_F, lsum = 0.f;
        for (int p = 0; p < cnt; p++) {
            int pi = lst + p;
            int jloc = (pi < PCAP) ? sp[pi] : g_pairs[bucket * MAXP + pairlo + pi];
            const float4* kr = (const float4*)ks + jloc * 16;
            int sw = jloc & 15;
            float a0 = 0.f, a1 = 0.f, a2 = 0.f, a3 = 0.f;
#pragma unroll
            for (int i = 0; i < 4; i++) {
                float4 k0 = kr[(4 * i + 0) ^ sw];
                float4 k1 = kr[(4 * i + 1) ^ sw];
                float4 k2 = kr[(4 * i + 2) ^ sw];
                float4 k3 = kr[(4 * i + 3) ^ sw];
                float4 q0 = q[4 * i + 0], q1 = q[4 * i + 1];
                float4 q2 = q[4 * i + 2], q3 = q[4 * i + 3];
                a0 = fmaf(q0.x, k0.x, a0); a0 = fmaf(q0.y, k0.y, a0);
                a0 = fmaf(q0.z, k0.z, a0); a0 = fmaf(q0.w, k0.w, a0);
                a1 = fmaf(q1.x, k1.x, a1); a1 = fmaf(q1.y, k1.y, a1);
                a1 = fmaf(q1.z, k1.z, a1); a1 = fmaf(q1.w, k1.w, a1);
                a2 = fmaf(q2.x, k2.x, a2); a2 = fmaf(q2.y, k2.y, a2);
                a2 = fmaf(q2.z, k2.z, a2); a2 = fmaf(q2.w, k2.w, a2);
                a3 = fmaf(q3.x, k3.x, a3); a3 = fmaf(q3.y, k3.y, a3);
                a3 = fmaf(q3.z, k3.z, a3); a3 = fmaf(q3.w, k3.w, a3);
            }
            float dot = (a0 + a1) + (a2 + a3);
            lm = fmaxf(lm, dot);
            lsum += dot;
        }
        size_t o = ((size_t)bh * Lq + l) * NB + bucket;
        g_pm2[o] = lm;
        g_ps2[o] = lsum;
    }
}

// ---------------- Stage 2: fused M-combine + top-45 + umap (1024 thr, shuffle argmax) ----
__global__ void __launch_bounds__(1024) kernel_topk() {
    int bh = blockIdx.x;
    __shared__ float v[Lq];
    __shared__ float sw[32];
    __shared__ int   si[32];
    int t = threadIdx.x;
    for (int i = t; i < Lq; i += 1024) {
        size_t base = ((size_t)bh * Lq + i) * NB;
        float m = -CUDART_INF_F, s = 0.f;
#pragma unroll
        for (int b = 0; b < NB; b++) {
            m = fmaxf(m, g_pm2[base + b]);
            s += g_ps2[base + b];
        }
        v[i] = m - s * (1.f / Lq);
        g_umap[bh * Lq + i] = -1;
    }
    __syncthreads();
    for (int u = 0; u < Uq; u++) {
        float best = -CUDART_INF_F;
        int   besti = Lq;
        for (int i = t; i < Lq; i += 1024) {
            float x = v[i];
            if (x > best) { best = x; besti = i; }   // strided ascending -> lowest idx kept
        }
#pragma unroll
        for (int o = 16; o > 0; o >>= 1) {
            float ov = __shfl_xor_sync(0xffffffffu, best, o);
            int   oi = __shfl_xor_sync(0xffffffffu, besti, o);
            if (ov > best || (ov == best && oi < besti)) { best = ov; besti = oi; }
        }
        if ((t & 31) == 0) { sw[t >> 5] = best; si[t >> 5] = besti; }
        __syncthreads();
        if (t < 32) {
            best = sw[t]; besti = si[t];
#pragma unroll
            for (int o = 16; o > 0; o >>= 1) {
                float ov = __shfl_xor_sync(0xffffffffu, best, o);
                int   oi = __shfl_xor_sync(0xffffffffu, besti, o);
                if (ov > best || (ov == best && oi < besti)) { best = ov; besti = oi; }
            }
            if (t == 0) {
                g_top[bh * Uq + u] = besti;
                g_umap[bh * Lq + besti] = u;
                v[besti] = -CUDART_INF_F;
            }
        }
        __syncthreads();
    }
}

// ---------------- Stage 3: flash attn, float4 LDS both loops ----------------
// 256 threads as (tu 0..15, tk 0..15). Score loop: d in float4 chunks.
// AV loop: thread owns contiguous d-quad 4*tk..4*tk+3 -> one LDS.128 per key.
__global__ void __launch_bounds__(256) kernel_attn(const float* __restrict__ Q,
                                                   const float* __restrict__ K,
                                                   const float* __restrict__ V) {
    __shared__ __align__(16) float Qs[Uq * 68];
    __shared__ __align__(16) float Ks[64 * 68];
    __shared__ __align__(16) float Vs[64 * 68];
    __shared__ __align__(16) float Ws[Uq * 68];
    int bh = blockIdx.y, kc = blockIdx.x;
    int b = bh >> 3, h = bh & 7;
    int tid = threadIdx.x;

    for (int e = tid; e < Uq * 16; e += 256) {
        int u = e >> 4, i = e & 15;
        int row = g_top[bh * Uq + u];
        *(float4*)&Qs[u * 68 + 4 * i] =
            *(const float4*)&Q[(((size_t)b * Lq + row) * Hq + h) * Dq + 4 * i];
    }
    int tu = tid >> 4, tk = tid & 15;
    float m_run[3], s_run[3];
    float4 acc[3];
#pragma unroll
    for (int r = 0; r < 3; r++) {
        m_run[r] = -CUDART_INF_F; s_run[r] = 0.f;
        acc[r] = make_float4(0.f, 0.f, 0.f, 0.f);
    }

    for (int sub = 0; sub < KCS / 64; sub++) {
        int k0 = kc * KCS + sub * 64;
        __syncthreads();
        for (int e = tid; e < 64 * 16; e += 256) {
            int k = e >> 4, i = e & 15;
            size_t go = (((size_t)b * Lq + k0 + k) * Hq + h) * Dq + 4 * i;
            *(float4*)&Ks[k * 68 + 4 * i] = *(const float4*)&K[go];
            *(float4*)&Vs[k * 68 + 4 * i] = *(const float4*)&V[go];
        }
        __syncthreads();

        float sc[3][4];
#pragma unroll
        for (int r = 0; r < 3; r++)
#pragma unroll
            for (int j = 0; j < 4; j++) sc[r][j] = 0.f;
#pragma unroll 4
        for (int d4 = 0; d4 < 16; d4++) {
            float4 qv[3];
#pragma unroll
            for (int r = 0; r < 3; r++) {
                int u = tu + 16 * r;
                qv[r] = (u < Uq) ? *(const float4*)&Qs[u * 68 + 4 * d4]
                                 : make_float4(0.f, 0.f, 0.f, 0.f);
            }
            float4 kv[4];
#pragma unroll
            for (int j = 0; j < 4; j++) kv[j] = *(const float4*)&Ks[(tk + 16 * j) * 68 + 4 * d4];
#pragma unroll
            for (int r = 0; r < 3; r++)
#pragma unroll
                for (int j = 0; j < 4; j++) {
                    float a = sc[r][j];
                    a = fmaf(qv[r].x, kv[j].x, a);
                    a = fmaf(qv[r].y, kv[j].y, a);
                    a = fmaf(qv[r].z, kv[j].z, a);
                    a = fmaf(qv[r].w, kv[j].w, a);
                    sc[r][j] = a;
                }
        }

#pragma unroll
        for (int r = 0; r < 3; r++) {
            int u = tu + 16 * r;
#pragma unroll
            for (int j = 0; j < 4; j++) sc[r][j] *= 0.125f;
            float bm = fmaxf(fmaxf(sc[r][0], sc[r][1]), fmaxf(sc[r][2], sc[r][3]));
#pragma unroll
            for (int o = 8; o > 0; o >>= 1)
                bm = fmaxf(bm, __shfl_xor_sync(0xffffffffu, bm, o));
            float mnew = fmaxf(m_run[r], bm);
            float f = expf(m_run[r] - mnew);
            acc[r].x *= f; acc[r].y *= f; acc[r].z *= f; acc[r].w *= f;
            s_run[r] *= f;
            float w[4], ws = 0.f;
#pragma unroll
            for (int j = 0; j < 4; j++) { w[j] = expf(sc[r][j] - mnew); ws += w[j]; }
#pragma unroll
            for (int o = 8; o > 0; o >>= 1)
                ws += __shfl_xor_sync(0xffffffffu, ws, o);
            s_run[r] += ws;
            m_run[r] = mnew;
            if (u < Uq) {
#pragma unroll
                for (int j = 0; j < 4; j++) Ws[u * 68 + tk + 16 * j] = w[j];
            }
        }
        __syncthreads();

#pragma unroll 4
        for (int k = 0; k < 64; k++) {
            float4 vv = *(const float4*)&Vs[k * 68 + 4 * tk];
#pragma unroll
            for (int r = 0; r < 3; r++) {
                int u = tu + 16 * r;
                float wv = (u < Uq) ? Ws[u * 68 + k] : 0.f;
                acc[r].x = fmaf(wv, vv.x, acc[r].x);
                acc[r].y = fmaf(wv, vv.y, acc[r].y);
                acc[r].z = fmaf(wv, vv.z, acc[r].z);
                acc[r].w = fmaf(wv, vv.w, acc[r].w);
            }
        }
    }

#pragma unroll
    for (int r = 0; r < 3; r++) {
        int u = tu + 16 * r;
        if (u < Uq) {
            *(float4*)&g_part[((bh * NKC + kc) * Uq + u) * Dq + 4 * tk] = acc[r];
            if (tk == 0) {
                g_cm[(bh * NKC + kc) * Uq + u] = m_run[r];
                g_cs[(bh * NKC + kc) * Uq + u] = s_run[r];
            }
        }
    }
}

// ---------------- Stage 4: V mean ----------------
__global__ void __launch_bounds__(256) kernel_meanpart(const float* __restrict__ V) {
    int lc = blockIdx.x;
    int bh = blockIdx.y;
    int b = bh >> 3, h = bh & 7;
    int tid = threadIdx.x;
    int d = tid & 63, c = tid >> 6;
    __shared__ float red[256];
    float s = 0.f;
    int lb = lc * 256 + c * 64;
    for (int i = 0; i < 64; i++)
        s += V[(((size_t)b * Lq + lb + i) * Hq + h) * Dq + d];
    red[tid] = s;
    __syncthreads();
    if (c == 0)
        g_meanp[(bh * 16 + lc) * Dq + d] = red[d] + red[64 + d] + red[128 + d] + red[192 + d];
}

__global__ void __launch_bounds__(256) kernel_meancomb() {
    int e = blockIdx.x * 256 + threadIdx.x;
    if (e >= BHq * Dq) return;
    int bh = e >> 6, d = e & 63;
    float s = 0.f;
#pragma unroll
    for (int lc = 0; lc < 16; lc++) s += g_meanp[(bh * 16 + lc) * Dq + d];
    g_meanv[bh * Dq + d] = s * (1.f / Lq);
}

// ---------------- Stage 5: single output kernel (mean fill OR top-row result) ----------
__global__ void __launch_bounds__(256) kernel_out(float4* __restrict__ out) {
    int i = blockIdx.x * 256 + threadIdx.x;      // float4 index
    int row = i >> 4;                            // (bh,l) flat
    int d4 = i & 15;
    int bh = row >> 12;
    int u = g_umap[row];
    if (u < 0) {
        out[i] = ((const float4*)g_meanv)[bh * 16 + d4];
    } else {
        float M = -CUDART_INF_F;
#pragma unroll
        for (int c = 0; c < NKC; c++) M = fmaxf(M, g_cm[(bh * NKC + c) * Uq + u]);
        float S = 0.f;
        float4 A = make_float4(0.f, 0.f, 0.f, 0.f);
#pragma unroll
        for (int c = 0; c < NKC; c++) {
            float f = expf(g_cm[(bh * NKC + c) * Uq + u] - M);
            S += g_cs[(bh * NKC + c) * Uq + u] * f;
            float4 p = ((const float4*)g_part)[((bh * NKC + c) * Uq + u) * 16 + d4];
            A.x += p.x * f; A.y += p.y * f; A.z += p.z * f; A.w += p.w * f;
        }
        float inv = 1.f / S;
        out[i] = make_float4(A.x * inv, A.y * inv, A.z * inv, A.w * inv);
    }
}

// ---------------- launch ----------------
extern "C" void kernel_launch(void* const* d_in, const int* in_sizes, int n_in,
                              void* d_out, int out_size) {
    const float* Q   = (const float*)d_in[0];
    const float* K   = (const float*)d_in[1];
    const float* V   = (const float*)d_in[2];
    const int*   idx = (const int*)d_in[3];
    float* out = (float*)d_out;

    const int M5_SMEM = (512 * 64 + 256 * 64) * 4 + PCAP * 4;   // 212,992 B
    static bool attr_set = false;
    if (!attr_set) {
        cudaFuncSetAttribute(kernel_m5, cudaFuncAttributeMaxDynamicSharedMemorySize, M5_SMEM);
        attr_set = true;
    }

    kernel_cnt     <<<Lq / 256, 256>>>(idx);
    kernel_scan    <<<NB, 256>>>();
    kernel_scatter <<<Lq / 256, 256>>>(idx);
    kernel_m5      <<<dim3(NB, BHq, 2), 512, M5_SMEM>>>(Q, K);
    kernel_topk    <<<BHq, 1024>>>();
    kernel_attn    <<<dim3(NKC, BHq), 256>>>(Q, K, V);
    kernel_meanpart<<<dim3(16, BHq), 256>>>(V);
    kernel_meancomb<<<(BHq * Dq + 255) / 256, 256>>>();
    kernel_out     <<<(BHq * Lq * Dq / 4) / 256, 256>>>((float4*)out);
}